// round 7
// baseline (speedup 1.0000x reference)
#include <cuda_runtime.h>
#include <cuda.h>
#include <math.h>

#define B  8
#define C  64
#define Hc 256
#define Wc 256
#define CR 128
#define HR 128
#define WR 128

__device__ float g_scores[B * CR];
__device__ int   g_idx[B * C];

// ---------------------------------------------------------------------------
// Kernel 1: analytic upsample-mean score (proven ~14us version).
// ---------------------------------------------------------------------------
__global__ void __launch_bounds__(256) scores_kernel(const float* __restrict__ readout) {
    __shared__ float wA[HR];
    __shared__ float red[8];
    const int tid = threadIdx.x;

    if (tid < HR) wA[tid] = 0.0f;
    __syncthreads();
    {
        const float cst = (float)(127.0 / 255.0);
        float pos = (float)tid * cst;
        int i0 = (int)pos;
        if (i0 > HR - 2) i0 = HR - 2;
        float w = pos - (float)i0;
        atomicAdd(&wA[i0], 1.0f - w);
        atomicAdd(&wA[i0 + 1], w);
    }
    __syncthreads();

    const int plane = blockIdx.x;
    const float4* __restrict__ src =
        (const float4*)(readout + (size_t)plane * (HR * WR));

    float acc0 = 0.f, acc1 = 0.f, acc2 = 0.f, acc3 = 0.f;
    #pragma unroll
    for (int half = 0; half < 2; half++) {
        float4 v[8];
        #pragma unroll
        for (int j = 0; j < 8; j++)
            v[j] = src[tid + (half * 8 + j) * 256];
        #pragma unroll
        for (int j = 0; j < 8; j++) {
            int base = (tid + (half * 8 + j) * 256) << 2;
            int row = base >> 7;
            int col = base & 127;
            float wr = wA[row];
            float s = wA[col] * v[j].x + wA[col + 1] * v[j].y +
                      wA[col + 2] * v[j].z + wA[col + 3] * v[j].w;
            if (j == 0 || j == 4) acc0 += wr * s;
            else if (j == 1 || j == 5) acc1 += wr * s;
            else if (j == 2 || j == 6) acc2 += wr * s;
            else acc3 += wr * s;
        }
    }

    float acc = (acc0 + acc1) + (acc2 + acc3);
    #pragma unroll
    for (int s = 16; s > 0; s >>= 1)
        acc += __shfl_down_sync(0xffffffffu, acc, s);
    if ((tid & 31) == 0) red[tid >> 5] = acc;
    __syncthreads();
    if (tid == 0) {
        float t = 0.f;
        #pragma unroll
        for (int w2 = 0; w2 < 8; w2++) t += red[w2];
        g_scores[plane] = t * (1.0f / (float)(Hc * Wc));
    }
}

// ---------------------------------------------------------------------------
// Kernel 2: per-batch descending bitonic sort (tie: lower index first).
// ---------------------------------------------------------------------------
__global__ void topk_kernel() {
    __shared__ float sv[CR];
    __shared__ int   si[CR];
    const int tid = threadIdx.x;
    const int b = blockIdx.x;

    sv[tid] = g_scores[b * CR + tid];
    si[tid] = tid;
    __syncthreads();

    for (int k = 2; k <= CR; k <<= 1) {
        for (int j = k >> 1; j > 0; j >>= 1) {
            int ixj = tid ^ j;
            if (ixj > tid) {
                float va = sv[tid], vb = sv[ixj];
                int   ia = si[tid], ib = si[ixj];
                bool first = (va > vb) || (va == vb && ia < ib);
                bool ascSeg = ((tid & k) == 0);
                bool doSwap = ascSeg ? (!first) : first;
                if (doSwap) {
                    sv[tid] = vb; sv[ixj] = va;
                    si[tid] = ib; si[ixj] = ia;
                }
            }
            __syncthreads();
        }
    }
    if (tid < C) g_idx[b * C + tid] = si[tid];
}

// ---------------------------------------------------------------------------
// TMA / mbarrier helpers
// ---------------------------------------------------------------------------
__device__ __forceinline__ uint32_t smem_u32(const void* p) {
    uint32_t a;
    asm("{ .reg .u64 t; cvta.to.shared.u64 t, %1; cvt.u32.u64 %0, t; }"
        : "=r"(a) : "l"(p));
    return a;
}
__device__ __forceinline__ void mbar_init(uint32_t a, uint32_t cnt) {
    asm volatile("mbarrier.init.shared.b64 [%0], %1;" :: "r"(a), "r"(cnt) : "memory");
}
__device__ __forceinline__ void mbar_expect(uint32_t a, uint32_t bytes) {
    asm volatile("mbarrier.arrive.expect_tx.shared.b64 _, [%0], %1;"
                 :: "r"(a), "r"(bytes) : "memory");
}
__device__ __forceinline__ void mbar_wait(uint32_t a, uint32_t ph) {
    asm volatile(
        "{\n\t.reg .pred P;\n"
        "W1_%=:\n\t"
        "mbarrier.try_wait.parity.acquire.cta.shared::cta.b64 P, [%0], %1, 0x989680;\n\t"
        "@P bra W2_%=;\n\t"
        "bra W1_%=;\n"
        "W2_%=:\n\t}"
        :: "r"(a), "r"(ph) : "memory");
}
__device__ __forceinline__ void tma3d(uint32_t dst, const CUtensorMap* tm,
                                      int c0, int c1, int c2, uint32_t mbar) {
    asm volatile(
        "cp.async.bulk.tensor.3d.shared::cta.global.tile.mbarrier::complete_tx::bytes "
        "[%0], [%1, {%2, %3, %4}], [%5];"
        :: "r"(dst), "l"(tm), "r"(c0), "r"(c1), "r"(c2), "r"(mbar) : "memory");
}

// ---------------------------------------------------------------------------
// Kernel 3: TMA-pipelined fused upsample + gated blend.
// Block = (plane, half). 8 tiles of 16 rows x 256 cols, 3-stage pipeline.
// Stage = 16KB x-tile + 8KB readout window, one mbarrier each.
// ---------------------------------------------------------------------------
#define NSTAGE     3
#define X_BYTES    16384
#define R_BYTES    8192
#define STAGE_SZ   (X_BYTES + R_BYTES)
#define TX_BYTES   (X_BYTES + R_BYTES)
#define NTILES     8

__global__ void __launch_bounds__(256) fuse_kernel(
    const __grid_constant__ CUtensorMap tmx,
    const __grid_constant__ CUtensorMap tmr,
    const float* __restrict__ weight,
    const float* __restrict__ bias,
    float* __restrict__ out)
{
    // 1024B-aligned dynamic smem: TMA destination alignment requirement.
    extern __shared__ __align__(1024) char sm[];
    __shared__ __align__(8) unsigned long long mbar[NSTAGE];

    const int tid = threadIdx.x;
    const int bx = blockIdx.x;
    const int plane = bx >> 1;          // b*C + c
    const int half  = bx & 1;
    const int b = plane >> 6;
    const int c = plane & (C - 1);
    const int ch = g_idx[plane];
    const int rplane = b * CR + ch;
    const int ybase = half * 128;

    uint32_t mb[NSTAGE];
    #pragma unroll
    for (int s = 0; s < NSTAGE; s++) mb[s] = smem_u32(&mbar[s]);

    if (tid == 0) {
        #pragma unroll
        for (int s = 0; s < NSTAGE; s++) mbar_init(mb[s], 1);
    }
    __syncthreads();

    if (tid == 0) {
        #pragma unroll
        for (int t = 0; t < NSTAGE; t++) {
            int y0 = ybase + t * 16;
            int iy_lo = (y0 * 127) / 255;
            uint32_t st = smem_u32(sm + t * STAGE_SZ);
            mbar_expect(mb[t], TX_BYTES);
            tma3d(st,           &tmx, 0, y0,    plane,  mb[t]);
            tma3d(st + X_BYTES, &tmr, 0, iy_lo, rplane, mb[t]);
        }
    }

    const float w0 = __ldg(weight + 2 * c);
    const float w1 = __ldg(weight + 2 * c + 1);
    const float bs = __ldg(bias + c);
    const float cst = (float)(127.0 / 255.0);

    const int r   = tid >> 4;           // 0..15 (row in tile)
    const int sl0 = tid & 15;           // base slot

    for (int t = 0; t < NTILES; t++) {
        const int s = t % NSTAGE;
        mbar_wait(mb[s], (t / NSTAGE) & 1);

        const float* __restrict__ xs =
            (const float*)(sm + s * STAGE_SZ);
        const float* __restrict__ rs =
            (const float*)(sm + s * STAGE_SZ + X_BYTES);

        const int y0 = ybase + t * 16;
        const int iy_lo = (y0 * 127) / 255;
        const int y = y0 + r;

        float posy = (float)y * cst;
        int iy0 = (int)posy;
        if (iy0 > HR - 2) iy0 = HR - 2;
        const float wy  = posy - (float)iy0;
        const float wy0 = 1.0f - wy;

        const float* __restrict__ s0 = rs + (iy0 - iy_lo) * WR;
        const float* __restrict__ s1 = s0 + WR;

        const size_t obase = ((size_t)plane * Hc + y) * Wc;

        #pragma unroll
        for (int k = 0; k < 4; k++) {
            const int slot = sl0 + 16 * k;
            const int x0 = slot << 2;
            float4 xq = ((const float4*)xs)[r * 64 + slot];
            float xv[4] = {xq.x, xq.y, xq.z, xq.w};
            float os[4];
            #pragma unroll
            for (int j = 0; j < 4; j++) {
                float posx = (float)(x0 + j) * cst;
                int ix0 = (int)posx;
                if (ix0 > WR - 2) ix0 = WR - 2;
                float wx = posx - (float)ix0;
                // reference order: interpolate H first, then W
                float a  = s0[ix0]     * wy0 + s1[ix0]     * wy;
                float bb = s0[ix0 + 1] * wy0 + s1[ix0 + 1] * wy;
                float rv = a * (1.0f - wx) + bb * wx;
                float tt = xv[j] * w0 + rv * w1 + bs;
                float gate = 1.0f / (1.0f + __expf(-tt));
                os[j] = xv[j] + gate * (rv - xv[j]);
            }
            __stcs((float4*)(out + obase + x0),
                   make_float4(os[0], os[1], os[2], os[3]));
        }

        __syncthreads();   // all threads done with stage s
        if (tid == 0 && t + NSTAGE < NTILES) {
            const int tn = t + NSTAGE;
            int yn = ybase + tn * 16;
            int iyn = (yn * 127) / 255;
            uint32_t st = smem_u32(sm + s * STAGE_SZ);
            mbar_expect(mb[s], TX_BYTES);
            tma3d(st,           &tmx, 0, yn,  plane,  mb[s]);
            tma3d(st + X_BYTES, &tmr, 0, iyn, rplane, mb[s]);
        }
    }
}

// ---------------------------------------------------------------------------
// Host side
// ---------------------------------------------------------------------------
typedef CUresult (*PFN_tmEncode)(
    CUtensorMap*, CUtensorMapDataType, cuuint32_t, void*,
    const cuuint64_t*, const cuuint64_t*, const cuuint32_t*, const cuuint32_t*,
    CUtensorMapInterleave, CUtensorMapSwizzle, CUtensorMapL2promotion,
    CUtensorMapFloatOOBfill);

extern "C" void kernel_launch(void* const* d_in, const int* in_sizes, int n_in,
                              void* d_out, int out_size)
{
    const float* x       = (const float*)d_in[0];
    const float* readout = (const float*)d_in[1];
    const float* weight  = (const float*)d_in[2];
    const float* bias    = (const float*)d_in[3];
    float* out = (float*)d_out;

    void* fn = nullptr;
    cudaDriverEntryPointQueryResult qres;
#if CUDART_VERSION >= 12050
    cudaGetDriverEntryPointByVersion("cuTensorMapEncodeTiled", &fn, 12030,
                                     cudaEnableDefault, &qres);
#else
    cudaGetDriverEntryPoint("cuTensorMapEncodeTiled", &fn,
                            cudaEnableDefault, &qres);
#endif
    PFN_tmEncode encode = (PFN_tmEncode)fn;

    CUtensorMap tmx, tmr;
    {
        cuuint64_t dims[3]    = {256, 256, 512};
        cuuint64_t strides[2] = {256 * 4, 256 * 256 * 4};
        cuuint32_t box[3]     = {256, 16, 1};
        cuuint32_t est[3]     = {1, 1, 1};
        encode(&tmx, CU_TENSOR_MAP_DATA_TYPE_FLOAT32, 3, (void*)x,
               dims, strides, box, est,
               CU_TENSOR_MAP_INTERLEAVE_NONE, CU_TENSOR_MAP_SWIZZLE_NONE,
               CU_TENSOR_MAP_L2_PROMOTION_L2_128B,
               CU_TENSOR_MAP_FLOAT_OOB_FILL_NONE);
    }
    {
        cuuint64_t dims[3]    = {128, 128, 1024};
        cuuint64_t strides[2] = {128 * 4, 128 * 128 * 4};
        cuuint32_t box[3]     = {128, 16, 1};
        cuuint32_t est[3]     = {1, 1, 1};
        encode(&tmr, CU_TENSOR_MAP_DATA_TYPE_FLOAT32, 3, (void*)readout,
               dims, strides, box, est,
               CU_TENSOR_MAP_INTERLEAVE_NONE, CU_TENSOR_MAP_SWIZZLE_NONE,
               CU_TENSOR_MAP_L2_PROMOTION_L2_128B,
               CU_TENSOR_MAP_FLOAT_OOB_FILL_NONE);
    }

    cudaFuncSetAttribute(fuse_kernel,
                         cudaFuncAttributeMaxDynamicSharedMemorySize,
                         NSTAGE * STAGE_SZ);

    scores_kernel<<<B * CR, 256>>>(readout);
    topk_kernel<<<B, CR>>>();
    fuse_kernel<<<B * C * 2, 256, NSTAGE * STAGE_SZ>>>(tmx, tmr, weight, bias, out);
}